// round 7
// baseline (speedup 1.0000x reference)
#include <cuda_runtime.h>
#include <cuda_bf16.h>
#include <cstdint>

#define NN 50000
#define EE 1600000
#define DIN 128
#define HID 64

// ---------------- device scratch ----------------
__device__ float g_deg[NN];
__device__ float g_dinv[NN];
__device__ float g_norm[EE];
__device__ __align__(16) float g_lin[NN * HID];   // linear output of current layer
__device__ __align__(16) float g_agg[NN * HID];   // aggregation buffer (layer 1)
__device__ __align__(16) float g_h1[NN * HID];    // layer-1 activation (residual)

// ---------------- helpers ----------------
__device__ __forceinline__ void red_add_f32x4(float4* p, float4 v) {
    asm volatile("red.global.add.v4.f32 [%0], {%1, %2, %3, %4};"
                 :: "l"(p), "f"(v.x), "f"(v.y), "f"(v.z), "f"(v.w)
                 : "memory");
}

// ---------------- kernels ----------------

__global__ void k_deg_init(int n) {
    int i = blockIdx.x * blockDim.x + threadIdx.x;
    if (i < n) g_deg[i] = 1.0f;   // self-loop weight
}

__global__ void k_deg_scatter(const int* __restrict__ ei, const float* __restrict__ ew, int e) {
    int t = blockIdx.x * blockDim.x + threadIdx.x;
    if (t < e) atomicAdd(&g_deg[ei[e + t]], ew[t]);
}

__global__ void k_dinv(int n) {
    int i = blockIdx.x * blockDim.x + threadIdx.x;
    if (i < n) {
        float d = g_deg[i];
        g_dinv[i] = (d > 0.0f) ? rsqrtf(d) : 0.0f;
    }
}

__global__ void k_norm(const int* __restrict__ ei, const float* __restrict__ ew, int e) {
    int t = blockIdx.x * blockDim.x + threadIdx.x;
    if (t < e) {
        int s = ei[t];
        int d = ei[e + t];
        g_norm[t] = g_dinv[s] * ew[t] * g_dinv[d];
    }
}

// H[M,64] = X[M,K] @ W[64,K]^T  (tiled 64x64, 4x4 microtile, fp32)
// Fused epilogue: lin = acc;  aggInit = acc * dinv[row]^2 + bias[col]
template <int K>
__global__ __launch_bounds__(256) void k_gemm(const float* __restrict__ X,
                                              const float* __restrict__ W,
                                              const float* __restrict__ bias,
                                              float* __restrict__ lin,
                                              float* __restrict__ aggInit, int M) {
    __shared__ float xs[64][68];
    __shared__ float wt[64][65];
    const int t  = threadIdx.x;
    const int tr = t >> 4;   // 0..15 row group
    const int tc = t & 15;   // 0..15 col group
    const int rowBase = blockIdx.x * 64;

    float acc[4][4];
#pragma unroll
    for (int i = 0; i < 4; i++)
#pragma unroll
        for (int j = 0; j < 4; j++) acc[i][j] = 0.0f;

#pragma unroll
    for (int k0 = 0; k0 < K; k0 += 64) {
#pragma unroll
        for (int i = 0; i < 4; i++) {
            int idx = t + i * 256;
            int r   = idx >> 4;
            int kq  = idx & 15;
            int gr  = rowBase + r;
            float4 v = make_float4(0.f, 0.f, 0.f, 0.f);
            if (gr < M) v = *reinterpret_cast<const float4*>(&X[(long long)gr * K + k0 + kq * 4]);
            *reinterpret_cast<float4*>(&xs[r][kq * 4]) = v;
        }
#pragma unroll
        for (int i = 0; i < 16; i++) {
            int idx = t + i * 256;
            int c = idx >> 6;
            int k = idx & 63;
            wt[k][c] = W[c * K + k0 + k];
        }
        __syncthreads();
#pragma unroll
        for (int k = 0; k < 64; k++) {
            float a[4], b[4];
#pragma unroll
            for (int i = 0; i < 4; i++) a[i] = xs[tr + i * 16][k];
#pragma unroll
            for (int j = 0; j < 4; j++) b[j] = wt[k][tc + j * 16];
#pragma unroll
            for (int i = 0; i < 4; i++)
#pragma unroll
                for (int j = 0; j < 4; j++) acc[i][j] = fmaf(a[i], b[j], acc[i][j]);
        }
        __syncthreads();
    }
#pragma unroll
    for (int i = 0; i < 4; i++) {
        int gr = rowBase + tr + i * 16;
        if (gr < M) {
            float s = g_dinv[gr];
            s *= s;
#pragma unroll
            for (int j = 0; j < 4; j++) {
                int c = tc + j * 16;
                float v = acc[i][j];
                lin[(long long)gr * HID + c] = v;
                aggInit[(long long)gr * HID + c] = fmaf(v, s, bias[c]);
            }
        }
    }
}

// agg[dst[e],:] += lin[src[e],:] * norm[e]   (16 threads/edge, float4 RED)
__global__ __launch_bounds__(512) void k_edge_scatter(const int* __restrict__ ei,
                               const float4* __restrict__ lin,
                               float4* __restrict__ agg, int e) {
    int t = blockIdx.x * blockDim.x + threadIdx.x;
    int ed = t >> 4;
    if (ed >= e) return;
    int q = t & 15;
    int s = __ldg(&ei[ed]);
    int d = __ldg(&ei[e + ed]);
    float nm = __ldg(&g_norm[ed]);
    float4 v = lin[s * 16 + q];
    v.x *= nm; v.y *= nm; v.z *= nm; v.w *= nm;
    red_add_f32x4(&agg[d * 16 + q], v);
}

// h1 = relu(agg)   (bias already folded into agg initializer) — float4
__global__ void k_relu(const float4* __restrict__ agg, float4* __restrict__ h1, int n16) {
    int t = blockIdx.x * blockDim.x + threadIdx.x;
    if (t < n16) {
        float4 v = agg[t];
        v.x = fmaxf(v.x, 0.0f); v.y = fmaxf(v.y, 0.0f);
        v.z = fmaxf(v.z, 0.0f); v.w = fmaxf(v.w, 0.0f);
        h1[t] = v;
    }
}

// out += h1   (bias already folded; out holds layer-2 aggregation) — float4
__global__ void k_final(float4* __restrict__ out, const float4* __restrict__ h1, int n16) {
    int t = blockIdx.x * blockDim.x + threadIdx.x;
    if (t < n16) {
        float4 o = out[t];
        float4 h = h1[t];
        o.x += h.x; o.y += h.y; o.z += h.z; o.w += h.w;
        out[t] = o;
    }
}

// ---------------- launch ----------------
extern "C" void kernel_launch(void* const* d_in, const int* in_sizes, int n_in,
                              void* d_out, int out_size) {
    const float* x  = (const float*)d_in[0];
    const int*   ei = (const int*)d_in[1];
    const float* ew = (const float*)d_in[2];
    const float* W1 = (const float*)d_in[3];
    const float* b1 = (const float*)d_in[4];
    const float* W2 = (const float*)d_in[5];
    const float* b2 = (const float*)d_in[6];
    float* out = (float*)d_out;

    const int n = in_sizes[0] / DIN;
    const int e = in_sizes[2];

    static float* p_lin = nullptr;
    static float* p_agg = nullptr;
    static float* p_h1  = nullptr;
    if (!p_lin) {
        void* p;
        cudaGetSymbolAddress(&p, g_lin); p_lin = (float*)p;
        cudaGetSymbolAddress(&p, g_agg); p_agg = (float*)p;
        cudaGetSymbolAddress(&p, g_h1);  p_h1  = (float*)p;
    }

    const int TB = 256;
    const int n16   = n * 16;          // rows of float4 (64 floats = 16 float4/row)
    const int gN    = (n + TB - 1) / TB;
    const int gE    = (e + TB - 1) / TB;
    const int gN16  = (n16 + TB - 1) / TB;
    const int gE16  = (int)(((long long)e * 16 + 511) / 512);
    const int gGemm = (n + 63) / 64;

    // ---- normalization (shared by both layers) ----
    k_deg_init<<<gN, TB>>>(n);
    k_deg_scatter<<<gE, TB>>>(ei, ew, e);
    k_dinv<<<gN, TB>>>(n);
    k_norm<<<gE, TB>>>(ei, ew, e);

    // ---- layer 1 ----
    k_gemm<DIN><<<gGemm, TB>>>(x, W1, b1, p_lin, p_agg, n);
    k_edge_scatter<<<gE16, 512>>>(ei, (const float4*)p_lin, (float4*)p_agg, e);
    k_relu<<<gN16, TB>>>((const float4*)p_agg, (float4*)p_h1, n16);

    // ---- layer 2 (aggregate directly into d_out) ----
    k_gemm<HID><<<gGemm, TB>>>(p_h1, W2, b2, p_lin, out, n);
    k_edge_scatter<<<gE16, 512>>>(ei, (const float4*)p_lin, (float4*)out, e);
    k_final<<<gN16, TB>>>((float4*)out, (const float4*)p_h1, n16);
}

// round 16
// speedup vs baseline: 1.2903x; 1.2903x over previous
#include <cuda_runtime.h>
#include <cuda_bf16.h>
#include <cstdint>

#define NN 50000
#define EE 1600000
#define DIN 128
#define HID 64

// ---------------- device scratch ----------------
__device__ float g_deg[NN];
__device__ int   g_cnt[NN];
__device__ float g_dinv[NN];
__device__ int   g_rowptr[NN + 1];
__device__ int   g_cursor[NN];
__device__ int2  g_csr[EE];        // packed (src, bits(norm)) in dst-sorted order
__device__ __align__(16) float g_lin[NN * HID];   // linear output of current layer
__device__ __align__(16) float g_h1[NN * HID];    // layer-1 activation (residual)

// ---------------- kernels ----------------

__global__ void k_deg_init(int n) {
    int i = blockIdx.x * blockDim.x + threadIdx.x;
    if (i < n) { g_deg[i] = 1.0f; g_cnt[i] = 0; }
}

// deg[dst] += ew ; cnt[dst] += 1   (fused degree + CSR histogram)
__global__ void k_deg_hist(const int* __restrict__ ei, const float* __restrict__ ew, int e) {
    int t = blockIdx.x * blockDim.x + threadIdx.x;
    if (t < e) {
        int d = ei[e + t];
        atomicAdd(&g_deg[d], ew[t]);
        atomicAdd(&g_cnt[d], 1);
    }
}

__global__ void k_dinv(int n) {
    int i = blockIdx.x * blockDim.x + threadIdx.x;
    if (i < n) {
        float d = g_deg[i];
        g_dinv[i] = (d > 0.0f) ? rsqrtf(d) : 0.0f;
    }
}

// Single-block exclusive scan of g_cnt -> g_rowptr / g_cursor (warp-shuffle based)
__global__ __launch_bounds__(1024) void k_scan(int n) {
    __shared__ int warpsum[32];
    __shared__ int carry_s;
    const int tid  = threadIdx.x;
    const int lane = tid & 31;
    const int wid  = tid >> 5;
    if (tid == 0) carry_s = 0;
    __syncthreads();
    for (int base = 0; base < n; base += 1024) {
        int i = base + tid;
        int v = (i < n) ? g_cnt[i] : 0;
        int x = v;
#pragma unroll
        for (int off = 1; off < 32; off <<= 1) {
            int t = __shfl_up_sync(0xFFFFFFFFu, x, off);
            if (lane >= off) x += t;
        }
        if (lane == 31) warpsum[wid] = x;
        __syncthreads();
        if (wid == 0) {
            int s = warpsum[lane];
#pragma unroll
            for (int off = 1; off < 32; off <<= 1) {
                int t = __shfl_up_sync(0xFFFFFFFFu, s, off);
                if (lane >= off) s += t;
            }
            warpsum[lane] = s;
        }
        __syncthreads();
        int warpoff = (wid == 0) ? 0 : warpsum[wid - 1];
        int carry   = carry_s;
        int excl    = carry + warpoff + x - v;
        if (i < n) { g_rowptr[i] = excl; g_cursor[i] = excl; }
        __syncthreads();
        if (tid == 1023) carry_s = carry + warpsum[31];
        __syncthreads();
    }
    if (tid == 0) g_rowptr[n] = carry_s;
}

// Bucket edges by dst with inline norm; single packed 8B store per edge.
__global__ void k_permute(const int* __restrict__ ei, const float* __restrict__ ew, int e) {
    int t = blockIdx.x * blockDim.x + threadIdx.x;
    if (t < e) {
        int s = ei[t];
        int d = ei[e + t];
        float nm = g_dinv[s] * ew[t] * g_dinv[d];
        int pos = atomicAdd(&g_cursor[d], 1);
        g_csr[pos] = make_int2(s, __float_as_int(nm));
    }
}

// H[M,64] = X[M,K] @ W[64,K]^T  (tiled 64x64, 4x4 microtile, fp32)
template <int K>
__global__ __launch_bounds__(256) void k_gemm(const float* __restrict__ X,
                                              const float* __restrict__ W,
                                              float* __restrict__ lin, int M) {
    __shared__ float xs[64][68];
    __shared__ float wt[64][65];
    const int t  = threadIdx.x;
    const int tr = t >> 4;
    const int tc = t & 15;
    const int rowBase = blockIdx.x * 64;

    float acc[4][4];
#pragma unroll
    for (int i = 0; i < 4; i++)
#pragma unroll
        for (int j = 0; j < 4; j++) acc[i][j] = 0.0f;

#pragma unroll
    for (int k0 = 0; k0 < K; k0 += 64) {
#pragma unroll
        for (int i = 0; i < 4; i++) {
            int idx = t + i * 256;
            int r   = idx >> 4;
            int kq  = idx & 15;
            int gr  = rowBase + r;
            float4 v = make_float4(0.f, 0.f, 0.f, 0.f);
            if (gr < M) v = *reinterpret_cast<const float4*>(&X[(long long)gr * K + k0 + kq * 4]);
            *reinterpret_cast<float4*>(&xs[r][kq * 4]) = v;
        }
#pragma unroll
        for (int i = 0; i < 16; i++) {
            int idx = t + i * 256;
            int c = idx >> 6;
            int k = idx & 63;
            wt[k][c] = W[c * K + k0 + k];
        }
        __syncthreads();
#pragma unroll
        for (int k = 0; k < 64; k++) {
            float a[4], b[4];
#pragma unroll
            for (int i = 0; i < 4; i++) a[i] = xs[tr + i * 16][k];
#pragma unroll
            for (int j = 0; j < 4; j++) b[j] = wt[k][tc + j * 16];
#pragma unroll
            for (int i = 0; i < 4; i++)
#pragma unroll
                for (int j = 0; j < 4; j++) acc[i][j] = fmaf(a[i], b[j], acc[i][j]);
        }
        __syncthreads();
    }
#pragma unroll
    for (int i = 0; i < 4; i++) {
        int gr = rowBase + tr + i * 16;
        if (gr < M) {
#pragma unroll
            for (int j = 0; j < 4; j++)
                lin[(long long)gr * HID + tc + j * 16] = acc[i][j];
        }
    }
}

// CSR gather: one warp per dst node, register accumulation, single write.
// MODE 0: out = relu(acc)            (layer 1 -> h1)
// MODE 1: out = acc + res[node]      (layer 2 -> final output, residual)
// Inner j-loop 4-way unrolled: 8 independent lin-loads in flight per step.
template <int MODE>
__global__ __launch_bounds__(256) void k_gather(const float* __restrict__ lin,
                                                const float* __restrict__ bias,
                                                const float* __restrict__ res,
                                                float* __restrict__ out, int n) {
    int w = (blockIdx.x * blockDim.x + threadIdx.x) >> 5;
    if (w >= n) return;
    const int lane = threadIdx.x & 31;
    const int start = g_rowptr[w];
    const int end   = g_rowptr[w + 1];

    float s = g_dinv[w];
    s *= s;
    float acc0 = fmaf(lin[w * HID + lane],      s, bias[lane]);
    float acc1 = fmaf(lin[w * HID + 32 + lane], s, bias[32 + lane]);

    for (int base = start; base < end; base += 32) {
        int idx = base + lane;
        int   src = 0;
        float nm  = 0.0f;
        if (idx < end) {
            int2 ent = g_csr[idx];
            src = ent.x;
            nm  = __int_as_float(ent.y);
        }
        int cnt = min(32, end - base);
        int j = 0;
        for (; j + 4 <= cnt; j += 4) {
            int   s0 = __shfl_sync(0xFFFFFFFFu, src, j);
            int   s1 = __shfl_sync(0xFFFFFFFFu, src, j + 1);
            int   s2 = __shfl_sync(0xFFFFFFFFu, src, j + 2);
            int   s3 = __shfl_sync(0xFFFFFFFFu, src, j + 3);
            float n0 = __shfl_sync(0xFFFFFFFFu, nm,  j);
            float n1 = __shfl_sync(0xFFFFFFFFu, nm,  j + 1);
            float n2 = __shfl_sync(0xFFFFFFFFu, nm,  j + 2);
            float n3 = __shfl_sync(0xFFFFFFFFu, nm,  j + 3);
            float a00 = lin[s0 * HID + lane];
            float a01 = lin[s0 * HID + 32 + lane];
            float a10 = lin[s1 * HID + lane];
            float a11 = lin[s1 * HID + 32 + lane];
            float a20 = lin[s2 * HID + lane];
            float a21 = lin[s2 * HID + 32 + lane];
            float a30 = lin[s3 * HID + lane];
            float a31 = lin[s3 * HID + 32 + lane];
            acc0 = fmaf(a00, n0, acc0);  acc1 = fmaf(a01, n0, acc1);
            acc0 = fmaf(a10, n1, acc0);  acc1 = fmaf(a11, n1, acc1);
            acc0 = fmaf(a20, n2, acc0);  acc1 = fmaf(a21, n2, acc1);
            acc0 = fmaf(a30, n3, acc0);  acc1 = fmaf(a31, n3, acc1);
        }
        for (; j < cnt; j++) {
            int   sj = __shfl_sync(0xFFFFFFFFu, src, j);
            float nj = __shfl_sync(0xFFFFFFFFu, nm,  j);
            acc0 = fmaf(lin[sj * HID + lane],      nj, acc0);
            acc1 = fmaf(lin[sj * HID + 32 + lane], nj, acc1);
        }
    }

    if (MODE == 0) {
        out[w * HID + lane]      = fmaxf(acc0, 0.0f);
        out[w * HID + 32 + lane] = fmaxf(acc1, 0.0f);
    } else {
        out[w * HID + lane]      = acc0 + res[w * HID + lane];
        out[w * HID + 32 + lane] = acc1 + res[w * HID + 32 + lane];
    }
}

// ---------------- launch ----------------
extern "C" void kernel_launch(void* const* d_in, const int* in_sizes, int n_in,
                              void* d_out, int out_size) {
    const float* x  = (const float*)d_in[0];
    const int*   ei = (const int*)d_in[1];
    const float* ew = (const float*)d_in[2];
    const float* W1 = (const float*)d_in[3];
    const float* b1 = (const float*)d_in[4];
    const float* W2 = (const float*)d_in[5];
    const float* b2 = (const float*)d_in[6];
    float* out = (float*)d_out;

    const int n = in_sizes[0] / DIN;
    const int e = in_sizes[2];

    static float* p_lin = nullptr;
    static float* p_h1  = nullptr;
    if (!p_lin) {
        void* p;
        cudaGetSymbolAddress(&p, g_lin); p_lin = (float*)p;
        cudaGetSymbolAddress(&p, g_h1);  p_h1  = (float*)p;
    }

    const int TB = 256;
    const int gN     = (n + TB - 1) / TB;
    const int gE     = (e + TB - 1) / TB;
    const int gGemm  = (n + 63) / 64;
    const int gGath  = (int)(((long long)n * 32 + TB - 1) / TB);

    // ---- normalization + CSR build (shared by both layers) ----
    k_deg_init<<<gN, TB>>>(n);
    k_deg_hist<<<gE, TB>>>(ei, ew, e);
    k_dinv<<<gN, TB>>>(n);
    k_scan<<<1, 1024>>>(n);
    k_permute<<<gE, TB>>>(ei, ew, e);

    // ---- layer 1 ----
    k_gemm<DIN><<<gGemm, TB>>>(x, W1, p_lin, n);
    k_gather<0><<<gGath, TB>>>(p_lin, b1, nullptr, p_h1, n);

    // ---- layer 2 ----
    k_gemm<HID><<<gGemm, TB>>>(p_h1, W2, p_lin, n);
    k_gather<1><<<gGath, TB>>>(p_lin, b2, p_h1, out, n);
}